// round 7
// baseline (speedup 1.0000x reference)
#include <cuda_runtime.h>
#include <cstdint>

// Problem constants
#define NTQ  512
#define NG   2048
#define NXF  16
#define HID  64
#define DLAG 4
#define TPRED (NTQ - DLAG)   // 508

// Scratch: wb[s][g][j] = relu(x_s@W_in+b_in)@W_xh + b_h  (pre-activation, bias folded)
__device__ float g_wb[(size_t)NTQ * NG * HID];   // 268 MB module-static

// ---------------- packed f32x2 helpers ----------------
__device__ __forceinline__ void ffma2(unsigned long long& d,
                                      unsigned long long a,
                                      unsigned long long b) {
    asm("fma.rn.f32x2 %0, %1, %2, %0;" : "+l"(d) : "l"(a), "l"(b));
}
__device__ __forceinline__ unsigned long long splat2(float v) {
    unsigned long long r;
    asm("mov.b64 %0, {%1, %1};" : "=l"(r) : "f"(v));
    return r;
}
__device__ __forceinline__ void unpack2(unsigned long long v, float& a, float& b) {
    asm("mov.b64 {%0, %1}, %2;" : "=f"(a), "=f"(b) : "l"(v));
}

// Fast accurate tanh: tanh(x) = 1 - 2/(e^{2x}+1), ~1e-7 abs error.
__device__ __forceinline__ float tanh_fast(float x) {
    float xc = fminf(fmaxf(x, -9.0f), 9.0f);
    float e;
    asm("ex2.approx.f32 %0, %1;" : "=f"(e) : "f"(xc * 2.8853900817779268f)); // e^{2x}
    float r;
    asm("rcp.approx.f32 %0, %1;" : "=f"(r) : "f"(e + 1.0f));
    return fmaf(-2.0f, r, 1.0f);
}

// ---------------- Kernel 1: wb_s = relu(x_s@W_in + b_in)@W_xh + b_h ----------------
// Second GEMM computed in two 32-wide halves to cap live registers (~105).
__global__ void __launch_bounds__(128, 1)
k_pre(const float* __restrict__ x,
      const float* __restrict__ W_in,
      const float* __restrict__ b_in,
      const float* __restrict__ W_xh,
      const float* __restrict__ b_h) {
    __shared__ ulonglong2 Wi[NXF * 16];             // 4 KB  (row i: 16 x 4 floats)
    __shared__ ulonglong2 Wx[HID * 16];             // 16 KB
    __shared__ unsigned long long bi[32], bh[32];   // biases as f32x2

    const int tid = threadIdx.x;
    {
        const ulonglong2* si = (const ulonglong2*)W_in;
        const ulonglong2* sx = (const ulonglong2*)W_xh;
        for (int k = tid; k < NXF * 16; k += 128) Wi[k] = si[k];
        for (int k = tid; k < HID * 16; k += 128) Wx[k] = sx[k];
        if (tid < 32) {
            bi[tid] = ((const unsigned long long*)b_in)[tid];
            bh[tid] = ((const unsigned long long*)b_h)[tid];
        }
    }
    __syncthreads();

    const size_t item = (size_t)blockIdx.x * 128 + tid;   // s*NG + g

    // load x row (16 floats)
    float xr[NXF];
    {
        const float4* xp = (const float4*)(x + item * NXF);
        #pragma unroll
        for (int q = 0; q < 4; q++) {
            float4 v = xp[q];
            xr[4 * q + 0] = v.x; xr[4 * q + 1] = v.y;
            xr[4 * q + 2] = v.z; xr[4 * q + 3] = v.w;
        }
    }

    // u = relu(x @ W_in + b_in)  -> ur[64] scalars
    float ur[HID];
    {
        unsigned long long u[32];
        #pragma unroll
        for (int j = 0; j < 32; j++) u[j] = bi[j];
        #pragma unroll
        for (int i = 0; i < NXF; i++) {
            unsigned long long s = splat2(xr[i]);
            #pragma unroll
            for (int j = 0; j < 16; j++) {
                ulonglong2 wv = Wi[i * 16 + j];
                ffma2(u[2 * j],     s, wv.x);
                ffma2(u[2 * j + 1], s, wv.y);
            }
        }
        #pragma unroll
        for (int j = 0; j < 32; j++) {
            float f0, f1;
            unpack2(u[j], f0, f1);
            ur[2 * j]     = fmaxf(f0, 0.0f);
            ur[2 * j + 1] = fmaxf(f1, 0.0f);
        }
    }

    // wb = u @ W_xh + b_h  — two 32-output halves, streamed to global
    ulonglong2* o = (ulonglong2*)(g_wb + item * HID);
    #pragma unroll 1
    for (int half = 0; half < 2; half++) {
        unsigned long long acc[16];
        #pragma unroll
        for (int j = 0; j < 8; j++) {
            acc[2 * j]     = bh[half * 16 + 2 * j];
            acc[2 * j + 1] = bh[half * 16 + 2 * j + 1];
        }
        #pragma unroll
        for (int i = 0; i < HID; i++) {          // full unroll: ur const-indexed
            unsigned long long s = splat2(ur[i]);
            #pragma unroll
            for (int j = 0; j < 8; j++) {
                ulonglong2 wv = Wx[i * 16 + half * 8 + j];
                ffma2(acc[2 * j],     s, wv.x);
                ffma2(acc[2 * j + 1], s, wv.y);
            }
        }
        #pragma unroll
        for (int j = 0; j < 8; j++) {
            ulonglong2 v;
            v.x = acc[2 * j];
            v.y = acc[2 * j + 1];
            o[half * 8 + j] = v;
        }
    }
}

// ---------------- Kernel 2: recurrence + output ----------------
// h lives in thread-private SMEM (hs[i][tid], conflict-free, no syncs needed).
// Live regs: acc[32] u64 (=64 f32) + temps  ->  no spills.
__global__ void __launch_bounds__(128, 1)
k_rec(const float* __restrict__ W_hh,
      const float* __restrict__ W_out,
      const float* __restrict__ b_out,
      float* __restrict__ out) {
    __shared__ ulonglong2 Wh[HID * 16];   // 16 KB
    __shared__ float hs[HID][128];        // 32 KB  (total static = 48 KB exactly)

    const int tid = threadIdx.x;
    {
        const ulonglong2* src = (const ulonglong2*)W_hh;
        for (int k = tid; k < HID * 16; k += 128) Wh[k] = src[k];
    }
    __syncthreads();

    const size_t item = (size_t)blockIdx.x * 128 + tid;   // t*NG + g, t in [0,T)

    // d = 0: h = tanh(wb[t])
    {
        const ulonglong2* w0 = (const ulonglong2*)(g_wb + item * HID);
        #pragma unroll
        for (int j = 0; j < 16; j++) {
            ulonglong2 v = w0[j];
            float f0, f1, f2, f3;
            unpack2(v.x, f0, f1);
            unpack2(v.y, f2, f3);
            hs[4 * j + 0][tid] = tanh_fast(f0);
            hs[4 * j + 1][tid] = tanh_fast(f1);
            hs[4 * j + 2][tid] = tanh_fast(f2);
            hs[4 * j + 3][tid] = tanh_fast(f3);
        }
    }

    float y = 0.0f;
    #pragma unroll 1
    for (int d = 1; d < DLAG; d++) {
        unsigned long long acc[32];
        {
            // wb[(t+d)*NG + g] == g_wb[item + d*NG]
            const ulonglong2* wd =
                (const ulonglong2*)(g_wb + (item + (size_t)d * NG) * HID);
            #pragma unroll
            for (int j = 0; j < 16; j++) {
                ulonglong2 v = wd[j];
                acc[2 * j]     = v.x;
                acc[2 * j + 1] = v.y;
            }
        }
        // acc += h @ W_hh   (64x64 matvec, packed f32x2; h from private SMEM)
        #pragma unroll 8
        for (int i = 0; i < HID; i++) {
            unsigned long long s = splat2(hs[i][tid]);
            #pragma unroll
            for (int j = 0; j < 16; j++) {
                ulonglong2 wv = Wh[i * 16 + j];
                ffma2(acc[2 * j],     s, wv.x);
                ffma2(acc[2 * j + 1], s, wv.y);
            }
        }
        if (d < DLAG - 1) {
            #pragma unroll
            for (int j = 0; j < 32; j++) {
                float f0, f1;
                unpack2(acc[j], f0, f1);
                hs[2 * j][tid]     = tanh_fast(f0);
                hs[2 * j + 1][tid] = tanh_fast(f1);
            }
        } else {
            float a0 = __ldg(b_out);           // uniform, L1-broadcast
            #pragma unroll
            for (int j = 0; j < 32; j++) {
                float f0, f1;
                unpack2(acc[j], f0, f1);
                a0 = fmaf(tanh_fast(f0), __ldg(W_out + 2 * j),     a0);
                a0 = fmaf(tanh_fast(f1), __ldg(W_out + 2 * j + 1), a0);
            }
            y = a0;
        }
    }

    // out[(t+D)*NG + g] == out[item + D*NG]
    out[item + (size_t)DLAG * NG] = y;
}

// Zero the first D time steps of the output
__global__ void k_zero(float* __restrict__ out) {
    int i = blockIdx.x * blockDim.x + threadIdx.x;
    if (i < DLAG * NG) out[i] = 0.0f;
}

extern "C" void kernel_launch(void* const* d_in, const int* in_sizes, int n_in,
                              void* d_out, int out_size) {
    const float* x     = (const float*)d_in[0];
    const float* W_in  = (const float*)d_in[1];
    const float* b_in  = (const float*)d_in[2];
    const float* W_xh  = (const float*)d_in[3];
    const float* W_hh  = (const float*)d_in[4];
    const float* b_h   = (const float*)d_in[5];
    const float* W_out = (const float*)d_in[6];
    const float* b_out = (const float*)d_in[7];
    float* out = (float*)d_out;

    (void)in_sizes; (void)n_in; (void)out_size;

    k_zero<<<(DLAG * NG + 255) / 256, 256>>>(out);

    // NT*NG items, 128 per block -> 8192 blocks (exact)
    k_pre<<<(NTQ * NG) / 128, 128>>>(x, W_in, b_in, W_xh, b_h);

    // T*NG items, 128 per block -> 8128 blocks (exact: 508*2048/128)
    k_rec<<<(TPRED * NG) / 128, 128>>>(W_hh, W_out, b_out, out);
}

// round 8
// speedup vs baseline: 1.1917x; 1.1917x over previous
#include <cuda_runtime.h>
#include <cstdint>

// Problem constants
#define NTQ  512
#define NG   2048
#define NXF  16
#define HID  64
#define DLAG 4
#define TPRED (NTQ - DLAG)   // 508

// Scratch: wb[s][g][j] = relu(x_s@W_in+b_in)@W_xh + b_h
__device__ float g_wb[(size_t)NTQ * NG * HID];   // 268 MB module-static

// ---------------- packed f32x2 helpers ----------------
__device__ __forceinline__ void ffma2(unsigned long long& d,
                                      unsigned long long a,
                                      unsigned long long b) {
    asm("fma.rn.f32x2 %0, %1, %2, %0;" : "+l"(d) : "l"(a), "l"(b));
}
__device__ __forceinline__ unsigned long long splat2(float v) {
    unsigned long long r;
    asm("mov.b64 %0, {%1, %1};" : "=l"(r) : "f"(v));
    return r;
}
__device__ __forceinline__ unsigned long long pack2(float a, float b) {
    unsigned long long r;
    asm("mov.b64 %0, {%1, %2};" : "=l"(r) : "f"(a), "f"(b));
    return r;
}
__device__ __forceinline__ void unpack2(unsigned long long v, float& a, float& b) {
    asm("mov.b64 {%0, %1}, %2;" : "=f"(a), "=f"(b) : "l"(v));
}

// Fast accurate tanh: tanh(x) = 1 - 2/(e^{2x}+1), ~1e-7 abs error.
__device__ __forceinline__ float tanh_fast(float x) {
    float xc = fminf(fmaxf(x, -9.0f), 9.0f);
    float e;
    asm("ex2.approx.f32 %0, %1;" : "=f"(e) : "f"(xc * 2.8853900817779268f)); // e^{2x}
    float r;
    asm("rcp.approx.f32 %0, %1;" : "=f"(r) : "f"(e + 1.0f));
    return fmaf(-2.0f, r, 1.0f);
}

// ---------------- Kernel 1: wb = relu(x@W_in + b_in)@W_xh + b_h ----------------
// 64 threads/block, 2 items/thread (128 items/block).
// W_xh in SMEM (16 KB), relu output staged in thread-private SMEM columns (32 KB).
// W_in / biases via __ldg (L1-broadcast). Static SMEM = exactly 48 KB.
// First 64 blocks also zero out[0 : D*NG].
__global__ void __launch_bounds__(64, 4)
k_pre(const float* __restrict__ x,
      const float* __restrict__ W_in,
      const float* __restrict__ b_in,
      const float* __restrict__ W_xh,
      const float* __restrict__ b_h,
      float* __restrict__ out) {
    __shared__ ulonglong2 Wx[HID * 16];   // 16 KB
    __shared__ float us[HID * 128];       // 32 KB (col = item-in-block)

    const int tid = threadIdx.x;
    {
        const ulonglong2* sx = (const ulonglong2*)W_xh;
        #pragma unroll
        for (int k = 0; k < 16; k++) Wx[k * 64 + tid] = sx[k * 64 + tid];
    }
    __syncthreads();

    // zero the first D time steps of the output (8192 floats over 64 blocks)
    if (blockIdx.x < 64) {
        out[blockIdx.x * 128 + tid] = 0.0f;
        out[blockIdx.x * 128 + tid + 64] = 0.0f;
    }

    const size_t base = (size_t)blockIdx.x * 128;

    // ---- GEMM1: u = relu(x @ W_in + b_in), staged to us[:, col] ----
    #pragma unroll 1
    for (int it = 0; it < 2; it++) {
        const int col = tid + it * 64;
        const size_t item = base + col;

        float xr[NXF];
        {
            const float4* xp = (const float4*)(x + item * NXF);
            #pragma unroll
            for (int q = 0; q < 4; q++) {
                float4 v = xp[q];
                xr[4 * q + 0] = v.x; xr[4 * q + 1] = v.y;
                xr[4 * q + 2] = v.z; xr[4 * q + 3] = v.w;
            }
        }

        unsigned long long u[32];
        #pragma unroll
        for (int j = 0; j < 32; j++)
            u[j] = __ldg((const unsigned long long*)b_in + j);

        #pragma unroll
        for (int i = 0; i < NXF; i++) {
            unsigned long long s = splat2(xr[i]);
            #pragma unroll
            for (int j = 0; j < 16; j++) {
                float4 w = __ldg((const float4*)W_in + i * 16 + j);
                ffma2(u[2 * j],     s, pack2(w.x, w.y));
                ffma2(u[2 * j + 1], s, pack2(w.z, w.w));
            }
        }
        #pragma unroll
        for (int j = 0; j < 32; j++) {
            float f0, f1;
            unpack2(u[j], f0, f1);
            us[(2 * j) * 128 + col]     = fmaxf(f0, 0.0f);
            us[(2 * j + 1) * 128 + col] = fmaxf(f1, 0.0f);
        }
    }
    // no sync: each thread reads only its own columns below

    // ---- GEMM2: wb = u @ W_xh + b_h, two 32-output halves, 2 items/thread ----
    ulonglong2* oA = (ulonglong2*)(g_wb + (base + tid) * HID);
    ulonglong2* oB = (ulonglong2*)(g_wb + (base + tid + 64) * HID);

    #pragma unroll 1
    for (int half = 0; half < 2; half++) {
        unsigned long long aA[16], aB[16];
        #pragma unroll
        for (int k = 0; k < 16; k++) {
            unsigned long long b2 = __ldg((const unsigned long long*)b_h + half * 16 + k);
            aA[k] = b2;
            aB[k] = b2;
        }
        #pragma unroll 4
        for (int i = 0; i < HID; i++) {
            unsigned long long sA = splat2(us[i * 128 + tid]);
            unsigned long long sB = splat2(us[i * 128 + tid + 64]);
            #pragma unroll
            for (int j = 0; j < 8; j++) {
                ulonglong2 wv = Wx[i * 16 + half * 8 + j];
                ffma2(aA[2 * j],     sA, wv.x);
                ffma2(aA[2 * j + 1], sA, wv.y);
                ffma2(aB[2 * j],     sB, wv.x);
                ffma2(aB[2 * j + 1], sB, wv.y);
            }
        }
        #pragma unroll
        for (int j = 0; j < 8; j++) {
            ulonglong2 vA, vB;
            vA.x = aA[2 * j]; vA.y = aA[2 * j + 1];
            vB.x = aB[2 * j]; vB.y = aB[2 * j + 1];
            oA[half * 8 + j] = vA;
            oB[half * 8 + j] = vB;
        }
    }
}

// ---------------- Kernel 2: recurrence + output ----------------
// 64 threads/block, 2 items/thread. h in thread-private SMEM columns.
// Full-width accumulators: 2 items x 64 outputs = 64 u64 regs.
__global__ void __launch_bounds__(64, 4)
k_rec(const float* __restrict__ W_hh,
      const float* __restrict__ W_out,
      const float* __restrict__ b_out,
      float* __restrict__ out) {
    __shared__ ulonglong2 Wh[HID * 16];   // 16 KB
    __shared__ float hs[HID * 128];       // 32 KB

    const int tid = threadIdx.x;
    {
        const ulonglong2* src = (const ulonglong2*)W_hh;
        #pragma unroll
        for (int k = 0; k < 16; k++) Wh[k * 64 + tid] = src[k * 64 + tid];
    }
    __syncthreads();

    const size_t itemA = (size_t)blockIdx.x * 128 + tid;   // t*NG + g
    const size_t itemB = itemA + 64;

    // d = 0: h = tanh(wb[t])
    {
        const ulonglong2* wA = (const ulonglong2*)(g_wb + itemA * HID);
        const ulonglong2* wB = (const ulonglong2*)(g_wb + itemB * HID);
        #pragma unroll
        for (int j = 0; j < 16; j++) {
            ulonglong2 vA = wA[j];
            ulonglong2 vB = wB[j];
            float a0, a1, a2, a3, b0, b1, b2, b3;
            unpack2(vA.x, a0, a1); unpack2(vA.y, a2, a3);
            unpack2(vB.x, b0, b1); unpack2(vB.y, b2, b3);
            hs[(4 * j + 0) * 128 + tid] = tanh_fast(a0);
            hs[(4 * j + 1) * 128 + tid] = tanh_fast(a1);
            hs[(4 * j + 2) * 128 + tid] = tanh_fast(a2);
            hs[(4 * j + 3) * 128 + tid] = tanh_fast(a3);
            hs[(4 * j + 0) * 128 + tid + 64] = tanh_fast(b0);
            hs[(4 * j + 1) * 128 + tid + 64] = tanh_fast(b1);
            hs[(4 * j + 2) * 128 + tid + 64] = tanh_fast(b2);
            hs[(4 * j + 3) * 128 + tid + 64] = tanh_fast(b3);
        }
    }

    float yA = 0.0f, yB = 0.0f;
    #pragma unroll 1
    for (int d = 1; d < DLAG; d++) {
        unsigned long long aA[32], aB[32];
        {
            const ulonglong2* wA =
                (const ulonglong2*)(g_wb + (itemA + (size_t)d * NG) * HID);
            const ulonglong2* wB =
                (const ulonglong2*)(g_wb + (itemB + (size_t)d * NG) * HID);
            #pragma unroll
            for (int j = 0; j < 16; j++) {
                ulonglong2 vA = wA[j];
                aA[2 * j] = vA.x; aA[2 * j + 1] = vA.y;
            }
            #pragma unroll
            for (int j = 0; j < 16; j++) {
                ulonglong2 vB = wB[j];
                aB[2 * j] = vB.x; aB[2 * j + 1] = vB.y;
            }
        }
        // acc += h @ W_hh  (64x64 matvec, 2 items share every Wh load)
        #pragma unroll 4
        for (int i = 0; i < HID; i++) {
            unsigned long long sA = splat2(hs[i * 128 + tid]);
            unsigned long long sB = splat2(hs[i * 128 + tid + 64]);
            #pragma unroll
            for (int j = 0; j < 16; j++) {
                ulonglong2 wv = Wh[i * 16 + j];
                ffma2(aA[2 * j],     sA, wv.x);
                ffma2(aA[2 * j + 1], sA, wv.y);
                ffma2(aB[2 * j],     sB, wv.x);
                ffma2(aB[2 * j + 1], sB, wv.y);
            }
        }
        if (d < DLAG - 1) {
            #pragma unroll
            for (int j = 0; j < 32; j++) {
                float f0, f1;
                unpack2(aA[j], f0, f1);
                hs[(2 * j) * 128 + tid]     = tanh_fast(f0);
                hs[(2 * j + 1) * 128 + tid] = tanh_fast(f1);
            }
            #pragma unroll
            for (int j = 0; j < 32; j++) {
                float f0, f1;
                unpack2(aB[j], f0, f1);
                hs[(2 * j) * 128 + tid + 64]     = tanh_fast(f0);
                hs[(2 * j + 1) * 128 + tid + 64] = tanh_fast(f1);
            }
        } else {
            float accA = __ldg(b_out);
            float accB = accA;
            #pragma unroll
            for (int j = 0; j < 32; j++) {
                float w0 = __ldg(W_out + 2 * j);
                float w1 = __ldg(W_out + 2 * j + 1);
                float f0, f1, g0, g1;
                unpack2(aA[j], f0, f1);
                unpack2(aB[j], g0, g1);
                accA = fmaf(tanh_fast(f0), w0, accA);
                accA = fmaf(tanh_fast(f1), w1, accA);
                accB = fmaf(tanh_fast(g0), w0, accB);
                accB = fmaf(tanh_fast(g1), w1, accB);
            }
            yA = accA;
            yB = accB;
        }
    }

    out[itemA + (size_t)DLAG * NG] = yA;
    out[itemB + (size_t)DLAG * NG] = yB;
}

extern "C" void kernel_launch(void* const* d_in, const int* in_sizes, int n_in,
                              void* d_out, int out_size) {
    const float* x     = (const float*)d_in[0];
    const float* W_in  = (const float*)d_in[1];
    const float* b_in  = (const float*)d_in[2];
    const float* W_xh  = (const float*)d_in[3];
    const float* W_hh  = (const float*)d_in[4];
    const float* b_h   = (const float*)d_in[5];
    const float* W_out = (const float*)d_in[6];
    const float* b_out = (const float*)d_in[7];
    float* out = (float*)d_out;

    (void)in_sizes; (void)n_in; (void)out_size;

    // NT*NG items, 128 per block -> 8192 blocks (also zeroes out[0:D*NG])
    k_pre<<<(NTQ * NG) / 128, 64>>>(x, W_in, b_in, W_xh, b_h, out);

    // T*NG items, 128 per block -> 8128 blocks (exact: 508*2048/128)
    k_rec<<<(TPRED * NG) / 128, 64>>>(W_hh, W_out, b_out, out);
}

// round 10
// speedup vs baseline: 1.5556x; 1.3053x over previous
#include <cuda_runtime.h>
#include <cstdint>

// Problem constants
#define NTQ  512
#define NG   2048
#define NXF  16
#define HID  64
#define DLAG 4
#define TPRED (NTQ - DLAG)   // 508

// Scratch, PAIR layout [s][c][g], c = j/2 in 0..31, each element a packed
// f32x2 pair {wb(s,2c,g), wb(s,2c+1,g)} stored as u64.
// u64 index: s*(32*NG) + c*NG + g
__device__ unsigned long long g_wb[(size_t)NTQ * 32 * NG];   // 268 MB

// ---------------- packed f32x2 helpers ----------------
__device__ __forceinline__ void ffma2(unsigned long long& d,
                                      unsigned long long a,
                                      unsigned long long b) {
    asm("fma.rn.f32x2 %0, %1, %2, %0;" : "+l"(d) : "l"(a), "l"(b));
}
__device__ __forceinline__ unsigned long long splat2(float v) {
    unsigned long long r;
    asm("mov.b64 %0, {%1, %1};" : "=l"(r) : "f"(v));
    return r;
}
__device__ __forceinline__ unsigned long long pack2(float a, float b) {
    unsigned long long r;
    asm("mov.b64 %0, {%1, %2};" : "=l"(r) : "f"(a), "f"(b));
    return r;
}
__device__ __forceinline__ void unpack2(unsigned long long v, float& a, float& b) {
    asm("mov.b64 {%0, %1}, %2;" : "=f"(a), "=f"(b) : "l"(v));
}

// Fast accurate tanh: tanh(x) = 1 - 2/(e^{2x}+1), ~1e-7 abs error.
__device__ __forceinline__ float tanh_fast(float x) {
    float xc = fminf(fmaxf(x, -9.0f), 9.0f);
    float e;
    asm("ex2.approx.f32 %0, %1;" : "=f"(e) : "f"(xc * 2.8853900817779268f));
    float r;
    asm("rcp.approx.f32 %0, %1;" : "=f"(r) : "f"(e + 1.0f));
    return fmaf(-2.0f, r, 1.0f);
}

// ---------------- Kernel 1: wb = relu(x@W_in + b_in)@W_xh + b_h ----------------
// 64 threads/block, 2 items/thread (128 items/block).
// Stores to pair layout [s][c][g]: coalesced LDG/STG.64 across the warp.
// First 64 blocks also zero out[0 : D*NG].
__global__ void __launch_bounds__(64, 4)
k_pre(const float* __restrict__ x,
      const float* __restrict__ W_in,
      const float* __restrict__ b_in,
      const float* __restrict__ W_xh,
      const float* __restrict__ b_h,
      float* __restrict__ out) {
    __shared__ ulonglong2 Wx[HID * 16];   // 16 KB
    __shared__ float us[HID * 128];       // 32 KB  (col = item-in-block)

    const int tid = threadIdx.x;
    {
        const ulonglong2* sx = (const ulonglong2*)W_xh;
        #pragma unroll
        for (int k = 0; k < 16; k++) Wx[k * 64 + tid] = sx[k * 64 + tid];
    }
    __syncthreads();

    if (blockIdx.x < 64) {
        out[blockIdx.x * 128 + tid] = 0.0f;
        out[blockIdx.x * 128 + tid + 64] = 0.0f;
    }

    const size_t base = (size_t)blockIdx.x * 128;
    const int s  = blockIdx.x >> 4;           // time index
    const int g0 = (blockIdx.x & 15) << 7;    // grid base

    // ---- GEMM1: u = relu(x @ W_in + b_in), staged to us[:, col] ----
    #pragma unroll 1
    for (int it = 0; it < 2; it++) {
        const int col = tid + it * 64;
        const size_t item = base + col;

        float xr[NXF];
        {
            const float4* xp = (const float4*)(x + item * NXF);
            #pragma unroll
            for (int q = 0; q < 4; q++) {
                float4 v = xp[q];
                xr[4 * q + 0] = v.x; xr[4 * q + 1] = v.y;
                xr[4 * q + 2] = v.z; xr[4 * q + 3] = v.w;
            }
        }

        unsigned long long u[32];
        #pragma unroll
        for (int j = 0; j < 32; j++)
            u[j] = __ldg((const unsigned long long*)b_in + j);

        #pragma unroll
        for (int i = 0; i < NXF; i++) {
            unsigned long long sv = splat2(xr[i]);
            #pragma unroll
            for (int j = 0; j < 16; j++) {
                float4 w = __ldg((const float4*)W_in + i * 16 + j);
                ffma2(u[2 * j],     sv, pack2(w.x, w.y));
                ffma2(u[2 * j + 1], sv, pack2(w.z, w.w));
            }
        }
        #pragma unroll
        for (int j = 0; j < 32; j++) {
            float f0, f1;
            unpack2(u[j], f0, f1);
            us[(2 * j) * 128 + col]     = fmaxf(f0, 0.0f);
            us[(2 * j + 1) * 128 + col] = fmaxf(f1, 0.0f);
        }
    }
    // no sync: each thread reads only its own columns below

    // ---- GEMM2: wb = u @ W_xh + b_h; store pairs to [s][c][g] ----
    unsigned long long* wp = g_wb + (size_t)s * (32 * NG) + g0 + tid;

    #pragma unroll 1
    for (int half = 0; half < 2; half++) {
        unsigned long long aA[16], aB[16];
        #pragma unroll
        for (int k = 0; k < 16; k++) {
            unsigned long long b2 = __ldg((const unsigned long long*)b_h + half * 16 + k);
            aA[k] = b2;
            aB[k] = b2;
        }
        #pragma unroll 4
        for (int i = 0; i < HID; i++) {
            unsigned long long sA = splat2(us[i * 128 + tid]);
            unsigned long long sB = splat2(us[i * 128 + tid + 64]);
            #pragma unroll
            for (int j = 0; j < 8; j++) {
                ulonglong2 wv = Wx[i * 16 + half * 8 + j];
                ffma2(aA[2 * j],     sA, wv.x);
                ffma2(aA[2 * j + 1], sA, wv.y);
                ffma2(aB[2 * j],     sB, wv.x);
                ffma2(aB[2 * j + 1], sB, wv.y);
            }
        }
        // pair index c = half*16 + k  (k = 0..15), coalesced u64 stores
        #pragma unroll
        for (int k = 0; k < 16; k++) {
            wp[(size_t)(half * 16 + k) * NG]      = aA[k];
            wp[(size_t)(half * 16 + k) * NG + 64] = aB[k];
        }
    }
}

// ---------------- Kernel 2: recurrence + output ----------------
// 64 threads/block, 2 items/thread. h in thread-private SMEM columns.
// wb pair loads are coalesced LDG.64 and land directly in the f32x2
// accumulator registers (no pack/unpack on the load path).
__global__ void __launch_bounds__(64, 4)
k_rec(const float* __restrict__ W_hh,
      const float* __restrict__ W_out,
      const float* __restrict__ b_out,
      float* __restrict__ out) {
    __shared__ ulonglong2 Wh[HID * 16];   // 16 KB
    __shared__ float hs[HID * 128];       // 32 KB

    const int tid = threadIdx.x;
    {
        const ulonglong2* src = (const ulonglong2*)W_hh;
        #pragma unroll
        for (int k = 0; k < 16; k++) Wh[k * 64 + tid] = src[k * 64 + tid];
    }
    __syncthreads();

    const int t0 = blockIdx.x >> 4;
    const int g  = ((blockIdx.x & 15) << 7) + tid;
    // pair pointer for (t0, c=0, g); c stride = NG, s stride = 32*NG
    const unsigned long long* wb0 = g_wb + (size_t)t0 * (32 * NG) + g;

    // ---- d = 0: h = tanh(wb[t0]) ----
    #pragma unroll
    for (int c = 0; c < 32; c++) {
        unsigned long long vA = __ldg(wb0 + (size_t)c * NG);
        unsigned long long vB = __ldg(wb0 + (size_t)c * NG + 64);
        float a0, a1, b0, b1;
        unpack2(vA, a0, a1);
        unpack2(vB, b0, b1);
        hs[(2 * c) * 128 + tid]          = tanh_fast(a0);
        hs[(2 * c + 1) * 128 + tid]      = tanh_fast(a1);
        hs[(2 * c) * 128 + tid + 64]     = tanh_fast(b0);
        hs[(2 * c + 1) * 128 + tid + 64] = tanh_fast(b1);
    }

    float yA = 0.0f, yB = 0.0f;
    #pragma unroll 1
    for (int d = 1; d < DLAG; d++) {
        const unsigned long long* wp = wb0 + (size_t)d * (32 * NG);
        unsigned long long aA[32], aB[32];
        #pragma unroll
        for (int c = 0; c < 32; c++) {
            aA[c] = __ldg(wp + (size_t)c * NG);
            aB[c] = __ldg(wp + (size_t)c * NG + 64);
        }
        // acc += h @ W_hh   (64x64 matvec, 2 items share every Wh load)
        #pragma unroll 4
        for (int i = 0; i < HID; i++) {
            unsigned long long sA = splat2(hs[i * 128 + tid]);
            unsigned long long sB = splat2(hs[i * 128 + tid + 64]);
            #pragma unroll
            for (int j = 0; j < 16; j++) {
                ulonglong2 wv = Wh[i * 16 + j];
                ffma2(aA[2 * j],     sA, wv.x);
                ffma2(aA[2 * j + 1], sA, wv.y);
                ffma2(aB[2 * j],     sB, wv.x);
                ffma2(aB[2 * j + 1], sB, wv.y);
            }
        }
        if (d < DLAG - 1) {
            #pragma unroll
            for (int c = 0; c < 32; c++) {
                float f0, f1;
                unpack2(aA[c], f0, f1);
                hs[(2 * c) * 128 + tid]     = tanh_fast(f0);
                hs[(2 * c + 1) * 128 + tid] = tanh_fast(f1);
            }
            #pragma unroll
            for (int c = 0; c < 32; c++) {
                float f0, f1;
                unpack2(aB[c], f0, f1);
                hs[(2 * c) * 128 + tid + 64]     = tanh_fast(f0);
                hs[(2 * c + 1) * 128 + tid + 64] = tanh_fast(f1);
            }
        } else {
            float accA = __ldg(b_out);
            float accB = accA;
            #pragma unroll
            for (int c = 0; c < 32; c++) {
                float w0 = __ldg(W_out + 2 * c);
                float w1 = __ldg(W_out + 2 * c + 1);
                float f0, f1, g0v, g1v;
                unpack2(aA[c], f0, f1);
                unpack2(aB[c], g0v, g1v);
                accA = fmaf(tanh_fast(f0), w0, accA);
                accA = fmaf(tanh_fast(f1), w1, accA);
                accB = fmaf(tanh_fast(g0v), w0, accB);
                accB = fmaf(tanh_fast(g1v), w1, accB);
            }
            yA = accA;
            yB = accB;
        }
    }

    // out[(t0+D)*NG + g]
    out[(size_t)(t0 + DLAG) * NG + g] = yA;
    out[(size_t)(t0 + DLAG) * NG + g + 64] = yB;
}

extern "C" void kernel_launch(void* const* d_in, const int* in_sizes, int n_in,
                              void* d_out, int out_size) {
    const float* x     = (const float*)d_in[0];
    const float* W_in  = (const float*)d_in[1];
    const float* b_in  = (const float*)d_in[2];
    const float* W_xh  = (const float*)d_in[3];
    const float* W_hh  = (const float*)d_in[4];
    const float* b_h   = (const float*)d_in[5];
    const float* W_out = (const float*)d_in[6];
    const float* b_out = (const float*)d_in[7];
    float* out = (float*)d_out;

    (void)in_sizes; (void)n_in; (void)out_size;

    // NT*NG items, 128 per block -> 8192 blocks (also zeroes out[0:D*NG])
    k_pre<<<(NTQ * NG) / 128, 64>>>(x, W_in, b_in, W_xh, b_h, out);

    // T*NG items, 128 per block -> 8128 blocks (508*2048/128)
    k_rec<<<(TPRED * NG) / 128, 64>>>(W_hh, W_out, b_out, out);
}

// round 11
// speedup vs baseline: 2.2452x; 1.4433x over previous
#include <cuda_runtime.h>
#include <cstdint>

// Problem constants
#define NTQ  512
#define NG   2048
#define NXF  16
#define HID  64
#define DLAG 4
#define TPRED (NTQ - DLAG)   // 508
#define TCHUNK 4             // t-values per block in k_rec (508 = 4*127)

// Scratch, PAIR layout [s][c][g], c = j/2 in 0..31, each element a packed
// f32 pair {wb(s,2c,g), wb(s,2c+1,g)} stored as u64 (low = even j).
__device__ unsigned long long g_wb[(size_t)NTQ * 32 * NG];   // 268 MB

// ---------------- packed f32x2 helpers ----------------
__device__ __forceinline__ void ffma2(unsigned long long& d,
                                      unsigned long long a,
                                      unsigned long long b) {
    asm("fma.rn.f32x2 %0, %1, %2, %0;" : "+l"(d) : "l"(a), "l"(b));
}
__device__ __forceinline__ unsigned long long splat2(float v) {
    unsigned long long r;
    asm("mov.b64 %0, {%1, %1};" : "=l"(r) : "f"(v));
    return r;
}
__device__ __forceinline__ unsigned long long pack2(float a, float b) {
    unsigned long long r;
    asm("mov.b64 %0, {%1, %2};" : "=l"(r) : "f"(a), "f"(b));
    return r;
}
__device__ __forceinline__ void unpack2(unsigned long long v, float& a, float& b) {
    asm("mov.b64 {%0, %1}, %2;" : "=f"(a), "=f"(b) : "l"(v));
}

// Fast accurate tanh: tanh(x) = 1 - 2/(e^{2x}+1), ~1e-7 abs error.
__device__ __forceinline__ float tanh_fast(float x) {
    float xc = fminf(fmaxf(x, -9.0f), 9.0f);
    float e;
    asm("ex2.approx.f32 %0, %1;" : "=f"(e) : "f"(xc * 2.8853900817779268f));
    float r;
    asm("rcp.approx.f32 %0, %1;" : "=f"(r) : "f"(e + 1.0f));
    return fmaf(-2.0f, r, 1.0f);
}

// split fp32 pair into bf16x2 hi word + bf16x2 lo correction word.
// low 16 bits = e0 (even index), high = e1.
__device__ __forceinline__ void split2(float e0, float e1,
                                       uint32_t& hi, uint32_t& lo) {
    asm("cvt.rn.satfinite.bf16x2.f32 %0, %1, %2;" : "=r"(hi) : "f"(e1), "f"(e0));
    float h0 = __uint_as_float(hi << 16);
    float h1 = __uint_as_float(hi & 0xFFFF0000u);
    float l0 = e0 - h0, l1 = e1 - h1;
    asm("cvt.rn.satfinite.bf16x2.f32 %0, %1, %2;" : "=r"(lo) : "f"(l1), "f"(l0));
}

// m16n8k16 row.col bf16 MMA, fp32 accumulate in place.
__device__ __forceinline__ void mma16816(float c[4],
                                         const uint32_t a[4],
                                         const uint32_t b[2]) {
    asm("mma.sync.aligned.m16n8k16.row.col.f32.bf16.bf16.f32 "
        "{%0,%1,%2,%3}, {%4,%5,%6,%7}, {%8,%9}, {%0,%1,%2,%3};"
        : "+f"(c[0]), "+f"(c[1]), "+f"(c[2]), "+f"(c[3])
        : "r"(a[0]), "r"(a[1]), "r"(a[2]), "r"(a[3]),
          "r"(b[0]), "r"(b[1]));
}

// ---------------- Kernel 1: wb = relu(x@W_in + b_in)@W_xh + b_h ----------------
// (unchanged from R10 — 64 threads/block, 2 items/thread, pair-layout stores)
__global__ void __launch_bounds__(64, 4)
k_pre(const float* __restrict__ x,
      const float* __restrict__ W_in,
      const float* __restrict__ b_in,
      const float* __restrict__ W_xh,
      const float* __restrict__ b_h,
      float* __restrict__ out) {
    __shared__ ulonglong2 Wx[HID * 16];   // 16 KB
    __shared__ float us[HID * 128];       // 32 KB

    const int tid = threadIdx.x;
    {
        const ulonglong2* sx = (const ulonglong2*)W_xh;
        #pragma unroll
        for (int k = 0; k < 16; k++) Wx[k * 64 + tid] = sx[k * 64 + tid];
    }
    __syncthreads();

    if (blockIdx.x < 64) {
        out[blockIdx.x * 128 + tid] = 0.0f;
        out[blockIdx.x * 128 + tid + 64] = 0.0f;
    }

    const size_t base = (size_t)blockIdx.x * 128;
    const int s  = blockIdx.x >> 4;
    const int g0 = (blockIdx.x & 15) << 7;

    #pragma unroll 1
    for (int it = 0; it < 2; it++) {
        const int col = tid + it * 64;
        const size_t item = base + col;

        float xr[NXF];
        {
            const float4* xp = (const float4*)(x + item * NXF);
            #pragma unroll
            for (int q = 0; q < 4; q++) {
                float4 v = xp[q];
                xr[4 * q + 0] = v.x; xr[4 * q + 1] = v.y;
                xr[4 * q + 2] = v.z; xr[4 * q + 3] = v.w;
            }
        }

        unsigned long long u[32];
        #pragma unroll
        for (int j = 0; j < 32; j++)
            u[j] = __ldg((const unsigned long long*)b_in + j);

        #pragma unroll
        for (int i = 0; i < NXF; i++) {
            unsigned long long sv = splat2(xr[i]);
            #pragma unroll
            for (int j = 0; j < 16; j++) {
                float4 w = __ldg((const float4*)W_in + i * 16 + j);
                ffma2(u[2 * j],     sv, pack2(w.x, w.y));
                ffma2(u[2 * j + 1], sv, pack2(w.z, w.w));
            }
        }
        #pragma unroll
        for (int j = 0; j < 32; j++) {
            float f0, f1;
            unpack2(u[j], f0, f1);
            us[(2 * j) * 128 + col]     = fmaxf(f0, 0.0f);
            us[(2 * j + 1) * 128 + col] = fmaxf(f1, 0.0f);
        }
    }

    unsigned long long* wp = g_wb + (size_t)s * (32 * NG) + g0 + tid;

    #pragma unroll 1
    for (int half = 0; half < 2; half++) {
        unsigned long long aA[16], aB[16];
        #pragma unroll
        for (int k = 0; k < 16; k++) {
            unsigned long long b2 = __ldg((const unsigned long long*)b_h + half * 16 + k);
            aA[k] = b2;
            aB[k] = b2;
        }
        #pragma unroll 4
        for (int i = 0; i < HID; i++) {
            unsigned long long sA = splat2(us[i * 128 + tid]);
            unsigned long long sB = splat2(us[i * 128 + tid + 64]);
            #pragma unroll
            for (int j = 0; j < 8; j++) {
                ulonglong2 wv = Wx[i * 16 + half * 8 + j];
                ffma2(aA[2 * j],     sA, wv.x);
                ffma2(aA[2 * j + 1], sA, wv.y);
                ffma2(aB[2 * j],     sB, wv.x);
                ffma2(aB[2 * j + 1], sB, wv.y);
            }
        }
        #pragma unroll
        for (int k = 0; k < 16; k++) {
            wp[(size_t)(half * 16 + k) * NG]      = aA[k];
            wp[(size_t)(half * 16 + k) * NG + 64] = aB[k];
        }
    }
}

// ---------------- Kernel 2: mma.sync (HMMA) recurrence ----------------
// 128 threads = 4 warps; warp handles 16 g-rows x 64 outputs; block loops
// over TCHUNK t-values. All operands register-resident; no SMEM.
// Per d-step: C <- wb[t+d] (fragment-exact u64 loads), then
// C += A_hi@B_hi + A_lo@B_hi + A_hi@B_lo  (bf16 hi/lo split, fp32 accum).
// D->A conversion (tanh + split) is thread-local: no memory round-trip for h.
__global__ void __launch_bounds__(128, 2)
k_rec(const float* __restrict__ W_hh,
      const float* __restrict__ W_out,
      const float* __restrict__ b_out,
      float* __restrict__ out) {
    const int lane = threadIdx.x & 31;
    const int warp = threadIdx.x >> 5;
    const int q  = lane & 3;    // col-pair / k-pair selector
    const int r4 = lane >> 2;   // row-in-group / B-col selector

    // g row for c0/c1 fragments (c2/c3 are row +8)
    const int gw = ((blockIdx.x & 31) << 6) + (warp << 4) + r4;
    const int tbase = (int)(blockIdx.x >> 5) * TCHUNK;

    // ---- B fragments: B[k][n] = W_hh[k][n], hi/lo split, built once ----
    uint32_t bhi[8][4][2], blo[8][4][2];
    #pragma unroll
    for (int nt = 0; nt < 8; nt++) {
        const int n = (nt << 3) + r4;
        #pragma unroll
        for (int kt = 0; kt < 4; kt++) {
            const int k0 = (kt << 4) + (q << 1);
            float w00 = __ldg(W_hh + k0 * HID + n);
            float w01 = __ldg(W_hh + (k0 + 1) * HID + n);
            float w10 = __ldg(W_hh + (k0 + 8) * HID + n);
            float w11 = __ldg(W_hh + (k0 + 9) * HID + n);
            split2(w00, w01, bhi[nt][kt][0], blo[nt][kt][0]);
            split2(w10, w11, bhi[nt][kt][1], blo[nt][kt][1]);
        }
    }

    #pragma unroll 1
    for (int tc = 0; tc < TCHUNK; tc++) {
        const int t = tbase + tc;
        const unsigned long long* wt = g_wb + (size_t)t * (32 * NG);

        uint32_t ahi[4][4], alo[4][4];

        // ---- d = 0: A <- split(tanh(wb[t])) ----
        #pragma unroll
        for (int kt = 0; kt < 4; kt++) {
            #pragma unroll
            for (int s = 0; s < 2; s++) {
                const int nt = 2 * kt + s;
                unsigned long long v0 = __ldg(wt + (size_t)((nt << 2) + q) * NG + gw);
                unsigned long long v1 = __ldg(wt + (size_t)((nt << 2) + q) * NG + gw + 8);
                float c0, c1, c2, c3;
                unpack2(v0, c0, c1);
                unpack2(v1, c2, c3);
                split2(tanh_fast(c0), tanh_fast(c1), ahi[kt][2 * s],     alo[kt][2 * s]);
                split2(tanh_fast(c2), tanh_fast(c3), ahi[kt][2 * s + 1], alo[kt][2 * s + 1]);
            }
        }

        #pragma unroll 1
        for (int d = 1; d < DLAG; d++) {
            const unsigned long long* wp = wt + (size_t)d * (32 * NG);
            float c[8][4];
            #pragma unroll
            for (int nt = 0; nt < 8; nt++) {
                unsigned long long v0 = __ldg(wp + (size_t)((nt << 2) + q) * NG + gw);
                unsigned long long v1 = __ldg(wp + (size_t)((nt << 2) + q) * NG + gw + 8);
                unpack2(v0, c[nt][0], c[nt][1]);
                unpack2(v1, c[nt][2], c[nt][3]);
            }
            #pragma unroll
            for (int nt = 0; nt < 8; nt++) {
                #pragma unroll
                for (int kt = 0; kt < 4; kt++) {
                    mma16816(c[nt], ahi[kt], bhi[nt][kt]);
                    mma16816(c[nt], alo[kt], bhi[nt][kt]);
                    mma16816(c[nt], ahi[kt], blo[nt][kt]);
                }
            }
            if (d < DLAG - 1) {
                // D -> tanh -> A (thread-local fragment identity)
                #pragma unroll
                for (int kt = 0; kt < 4; kt++) {
                    #pragma unroll
                    for (int s = 0; s < 2; s++) {
                        const int nt = 2 * kt + s;
                        split2(tanh_fast(c[nt][0]), tanh_fast(c[nt][1]),
                               ahi[kt][2 * s], alo[kt][2 * s]);
                        split2(tanh_fast(c[nt][2]), tanh_fast(c[nt][3]),
                               ahi[kt][2 * s + 1], alo[kt][2 * s + 1]);
                    }
                }
            } else {
                // epilogue: y = tanh(D) @ W_out + b_out, reduce over 4-lane group
                float p0 = 0.0f, p1 = 0.0f;
                #pragma unroll
                for (int nt = 0; nt < 8; nt++) {
                    float w0 = __ldg(W_out + (nt << 3) + (q << 1));
                    float w1 = __ldg(W_out + (nt << 3) + (q << 1) + 1);
                    p0 = fmaf(tanh_fast(c[nt][0]), w0, p0);
                    p0 = fmaf(tanh_fast(c[nt][1]), w1, p0);
                    p1 = fmaf(tanh_fast(c[nt][2]), w0, p1);
                    p1 = fmaf(tanh_fast(c[nt][3]), w1, p1);
                }
                p0 += __shfl_xor_sync(0xffffffffu, p0, 1);
                p0 += __shfl_xor_sync(0xffffffffu, p0, 2);
                p1 += __shfl_xor_sync(0xffffffffu, p1, 1);
                p1 += __shfl_xor_sync(0xffffffffu, p1, 2);
                if (q == 0) {
                    const float bo = __ldg(b_out);
                    out[(size_t)(t + DLAG) * NG + gw]     = p0 + bo;
                    out[(size_t)(t + DLAG) * NG + gw + 8] = p1 + bo;
                }
            }
        }
    }
}

extern "C" void kernel_launch(void* const* d_in, const int* in_sizes, int n_in,
                              void* d_out, int out_size) {
    const float* x     = (const float*)d_in[0];
    const float* W_in  = (const float*)d_in[1];
    const float* b_in  = (const float*)d_in[2];
    const float* W_xh  = (const float*)d_in[3];
    const float* W_hh  = (const float*)d_in[4];
    const float* b_h   = (const float*)d_in[5];
    const float* W_out = (const float*)d_in[6];
    const float* b_out = (const float*)d_in[7];
    float* out = (float*)d_out;

    (void)in_sizes; (void)n_in; (void)out_size;

    // NT*NG items, 128 per block -> 8192 blocks (also zeroes out[0:D*NG])
    k_pre<<<(NTQ * NG) / 128, 64>>>(x, W_in, b_in, W_xh, b_h, out);

    // 32 g-blocks x 127 t-chunks = 4064 blocks, 4 warps each
    k_rec<<<32 * (TPRED / TCHUNK), 128>>>(W_hh, W_out, b_out, out);
}